// round 6
// baseline (speedup 1.0000x reference)
#include <cuda_runtime.h>
#include <cuda_bf16.h>
#include <math.h>
#include <stdint.h>

// Problem constants
#define Bb   2
#define Tt   2048
#define Dd   2048
#define Hh   16
#define HDd  128
#define LATd 512
#define RDd  64
#define CDd  64
#define Mrows (Bb*Tt)   // 4096

// ---------------------------------------------------------------------------
// Scratch (static device globals; no allocation allowed)
// ---------------------------------------------------------------------------
__device__ float g_q [Mrows * (Hh*HDd)];
__device__ float g_kv[Mrows * (2*LATd)];
__device__ float g_kr[Mrows * RDd];
__device__ float g_kc[Mrows * (Hh*CDd)];
__device__ float g_v [Mrows * (Hh*HDd)];
__device__ float g_ao[Mrows * (Hh*HDd)];

// ---------------------------------------------------------------------------
// Common tf32 helpers (fragment layouts HW-validated in rounds 3-5)
// ---------------------------------------------------------------------------
__device__ __forceinline__ uint32_t f2tf32(float f) {
    uint32_t r;
    asm("cvt.rna.tf32.f32 %0, %1;" : "=r"(r) : "f"(f));
    return r;
}

__device__ __forceinline__ void mma_tf32(
    float& c0, float& c1, float& c2, float& c3,
    uint32_t a0, uint32_t a1, uint32_t a2, uint32_t a3,
    uint32_t b0, uint32_t b1)
{
    asm volatile(
        "mma.sync.aligned.m16n8k8.row.col.f32.tf32.tf32.f32 "
        "{%0,%1,%2,%3}, {%4,%5,%6,%7}, {%8,%9}, {%0,%1,%2,%3};\n"
        : "+f"(c0), "+f"(c1), "+f"(c2), "+f"(c3)
        : "r"(a0), "r"(a1), "r"(a2), "r"(a3), "r"(b0), "r"(b1));
}

__device__ __forceinline__ void cp_async16(uint32_t dst_smem, const void* src, int src_bytes) {
    asm volatile("cp.async.cg.shared.global [%0], [%1], 16, %2;\n"
                 :: "r"(dst_smem), "l"(src), "r"(src_bytes));
}
#define CP_COMMIT() asm volatile("cp.async.commit_group;\n" ::: "memory")
#define CP_WAIT1()  asm volatile("cp.async.wait_group 1;\n" ::: "memory")

// ---------------------------------------------------------------------------
// TF32 GEMM, cp.async double-buffered: C(M,N) = A(M,K) @ W(N,K)^T + bias(N)
// 128x256x32 block tile, 256 threads (8 warps), warp tile 64x64 (4x8 atoms).
// smem holds raw fp32 (2 stages); tf32 conversion on fragment load.
// M%128==0, K%32==0. N guarded (zero-filled cp.async + epilogue guard).
// ---------------------------------------------------------------------------
#define BM 128
#define BN 256
#define BK 32
#define GST 36                        // smem row stride (floats), %32==4
#define G_ASZ (BM*GST)                // 4608 floats per A stage
#define G_BSZ (BN*GST)                // 9216 floats per B stage
#define GEMM_SMEM_BYTES ((2*G_ASZ + 2*G_BSZ) * 4)   // 110592 B

__global__ void __launch_bounds__(256, 1) gemm_tf32(
    const float* __restrict__ A, int lda,
    const float* __restrict__ W,
    const float* __restrict__ bias,
    float* __restrict__ C, int ldc,
    int M, int N, int K)
{
    extern __shared__ float smemf[];
    // layout: As stage0 | As stage1 | Bs stage0 | Bs stage1
    const uint32_t smem_u32 = (uint32_t)__cvta_generic_to_shared(smemf);

    const int tid  = threadIdx.x;
    const int warp = tid >> 5;
    const int lane = tid & 31;
    const int g    = lane >> 2;
    const int tg   = lane & 3;
    const int wm   = warp & 1;        // 2 warps along M (64 rows each)
    const int wn   = warp >> 1;       // 4 warps along N (64 cols each)
    const int bm   = blockIdx.y * BM;
    const int bn   = blockIdx.x * BN;
    const int wr0  = wm * 64;
    const int wn0  = wn * 64;

    const int lrow0 = tid >> 3;       // load mapping: slot>>3
    const int lk4   = (tid & 7) * 4;

    float acc[4][8][4];
    #pragma unroll
    for (int mi = 0; mi < 4; mi++)
        #pragma unroll
        for (int ni = 0; ni < 8; ni++)
            #pragma unroll
            for (int r = 0; r < 4; r++) acc[mi][ni][r] = 0.f;

    const int ntiles = K / BK;

    auto prefetch = [&](int k0, int stage) {
        // A: 128 rows x 32 cols = 1024 float4 slots -> 4 per thread
        #pragma unroll
        for (int it = 0; it < 4; it++) {
            int row = lrow0 + it * 32;
            uint32_t adst = smem_u32 + (uint32_t)((stage*G_ASZ + row*GST + lk4) * 4);
            cp_async16(adst, A + (size_t)(bm + row) * lda + k0 + lk4, 16);
        }
        // B: 256 rows x 32 cols = 2048 float4 slots -> 8 per thread
        #pragma unroll
        for (int it = 0; it < 8; it++) {
            int row = lrow0 + it * 32;
            int nrow = bn + row;
            uint32_t bdst = smem_u32 + (uint32_t)((2*G_ASZ + stage*G_BSZ + row*GST + lk4) * 4);
            cp_async16(bdst, W + (size_t)(nrow < N ? nrow : 0) * K + k0 + lk4,
                       nrow < N ? 16 : 0);
        }
    };

    prefetch(0, 0);
    CP_COMMIT();

    for (int t = 0; t < ntiles; t++) {
        if (t + 1 < ntiles) prefetch((t + 1) * BK, (t + 1) & 1);
        CP_COMMIT();
        CP_WAIT1();
        __syncthreads();

        const float* Asb = smemf + (t & 1) * G_ASZ;
        const float* Bsb = smemf + 2*G_ASZ + (t & 1) * G_BSZ;

        #pragma unroll
        for (int kk = 0; kk < BK; kk += 8) {
            uint32_t af[4][4], bf[8][2];
            #pragma unroll
            for (int mi = 0; mi < 4; mi++) {
                int r0 = wr0 + mi * 16 + g;
                af[mi][0] = f2tf32(Asb[r0*GST     + kk + tg]);
                af[mi][1] = f2tf32(Asb[(r0+8)*GST + kk + tg]);
                af[mi][2] = f2tf32(Asb[r0*GST     + kk + tg + 4]);
                af[mi][3] = f2tf32(Asb[(r0+8)*GST + kk + tg + 4]);
            }
            #pragma unroll
            for (int ni = 0; ni < 8; ni++) {
                int n0 = wn0 + ni * 8 + g;
                bf[ni][0] = f2tf32(Bsb[n0*GST + kk + tg]);
                bf[ni][1] = f2tf32(Bsb[n0*GST + kk + tg + 4]);
            }
            #pragma unroll
            for (int mi = 0; mi < 4; mi++)
                #pragma unroll
                for (int ni = 0; ni < 8; ni++)
                    mma_tf32(acc[mi][ni][0], acc[mi][ni][1],
                             acc[mi][ni][2], acc[mi][ni][3],
                             af[mi][0], af[mi][1], af[mi][2], af[mi][3],
                             bf[ni][0], bf[ni][1]);
        }
        __syncthreads();
    }

    #pragma unroll
    for (int mi = 0; mi < 4; mi++) {
        int row0 = bm + wr0 + mi * 16 + g;
        #pragma unroll
        for (int ni = 0; ni < 8; ni++) {
            int col = bn + wn0 + ni * 8 + 2 * tg;
            if (col < N) {
                float b0 = bias[col];
                float b1 = bias[col + 1];
                float* p0 = C + (size_t)row0 * ldc + col;
                float* p1 = C + (size_t)(row0 + 8) * ldc + col;
                p0[0] = acc[mi][ni][0] + b0;
                p0[1] = acc[mi][ni][1] + b1;
                p1[0] = acc[mi][ni][2] + b0;
                p1[1] = acc[mi][ni][3] + b1;
            }
        }
    }
}

// ---------------------------------------------------------------------------
// RoPE (rotate-half). RD=64, half=32.
// ---------------------------------------------------------------------------
__device__ __forceinline__ void rope_pair(float* p, int i, int t)
{
    float inv_freq = powf(10000.f, -(float)i / 32.f);
    float ang = (float)t * inv_freq;
    float s, c;
    sincosf(ang, &s, &c);
    float x1 = p[i];
    float x2 = p[i + 32];
    p[i]      = x1 * c - x2 * s;
    p[i + 32] = x2 * c + x1 * s;
}

__global__ void rope_kr_kernel(float* __restrict__ kr)
{
    int row = blockIdx.x;
    int t   = row & (Tt - 1);
    rope_pair(kr + (size_t)row * RDd, threadIdx.x, t);
}

__global__ void rope_q_kernel(float* __restrict__ qb)
{
    int row = blockIdx.x;
    int h   = blockIdx.y;
    int t   = row & (Tt - 1);
    rope_pair(qb + (size_t)row * (Hh*HDd) + h*HDd + CDd, threadIdx.x, t);
}

// ---------------------------------------------------------------------------
// Tensor-core flash attention (tf32 mma) — unchanged from round 4/5.
// ---------------------------------------------------------------------------
#define AT_SQ 132
#define AT_SV 136
#define AT_SP 68
#define AT_SMEM_BYTES ((64*AT_SQ + 64*AT_SV + 64*AT_SP) * 4)

__global__ void __launch_bounds__(128, 2) attn_mma_kernel(
    const float* __restrict__ q,
    const float* __restrict__ kc,
    const float* __restrict__ kr,
    const float* __restrict__ v,
    float* __restrict__ o)
{
    extern __shared__ uint32_t smu[];
    uint32_t* Ks = smu;
    uint32_t* Vs = Ks + 64*AT_SQ;
    uint32_t* Ps = Vs + 64*AT_SV;

    const int qt   = (Tt/64 - 1) - blockIdx.x;
    const int h    = blockIdx.y;
    const int b    = blockIdx.z;
    const int tid  = threadIdx.x;
    const int warp = tid >> 5;
    const int lane = tid & 31;
    const int g    = lane >> 2;
    const int tg   = lane & 3;
    const int m0   = warp * 16;
    const int qbase = qt * 64;
    const size_t rowbase = (size_t)b * Tt;
    const float scale = 0.08838834764831845f;

    uint32_t aq[16][4];
    {
        const float* qA = q + (rowbase + qbase + m0 + g) * (Hh*HDd) + h*HDd;
        const float* qB = qA + 8 * (Hh*HDd);
        #pragma unroll
        for (int ks = 0; ks < 16; ks++) {
            int k0 = ks * 8;
            aq[ks][0] = f2tf32(qA[k0 + tg]);
            aq[ks][1] = f2tf32(qB[k0 + tg]);
            aq[ks][2] = f2tf32(qA[k0 + tg + 4]);
            aq[ks][3] = f2tf32(qB[k0 + tg + 4]);
        }
    }

    float oacc[16][4];
    #pragma unroll
    for (int na = 0; na < 16; na++)
        #pragma unroll
        for (int r = 0; r < 4; r++) oacc[na][r] = 0.f;

    float mA = -INFINITY, mB = -INFINITY;
    float lA = 0.f, lB = 0.f;

    for (int kb = 0; kb <= qt; kb++) {
        const int kbase = kb * 64;

        for (int i = tid; i < 64*32; i += 128) {
            int rr = i >> 5;
            int c4 = i & 31;
            size_t trow = rowbase + kbase + rr;
            float4 kval;
            if (c4 < 16)
                kval = *(const float4*)(kc + trow * (Hh*CDd) + h*CDd + c4*4);
            else
                kval = *(const float4*)(kr + trow * RDd + (c4-16)*4);
            uint4 kt;
            kt.x = f2tf32(kval.x); kt.y = f2tf32(kval.y);
            kt.z = f2tf32(kval.z); kt.w = f2tf32(kval.w);
            *(uint4*)&Ks[rr*AT_SQ + c4*4] = kt;

            float4 vv = *(const float4*)(v + trow * (Hh*HDd) + h*HDd + c4*4);
            uint4 vt;
            vt.x = f2tf32(vv.x); vt.y = f2tf32(vv.y);
            vt.z = f2tf32(vv.z); vt.w = f2tf32(vv.w);
            *(uint4*)&Vs[rr*AT_SV + c4*4] = vt;
        }
        __syncthreads();

        float sacc[8][4];
        #pragma unroll
        for (int na = 0; na < 8; na++)
            #pragma unroll
            for (int r = 0; r < 4; r++) sacc[na][r] = 0.f;

        #pragma unroll
        for (int ks = 0; ks < 16; ks++) {
            #pragma unroll
            for (int na = 0; na < 8; na++) {
                uint32_t b0 = Ks[(na*8 + g)*AT_SQ + ks*8 + tg];
                uint32_t b1 = Ks[(na*8 + g)*AT_SQ + ks*8 + tg + 4];
                mma_tf32(sacc[na][0], sacc[na][1], sacc[na][2], sacc[na][3],
                         aq[ks][0], aq[ks][1], aq[ks][2], aq[ks][3], b0, b1);
            }
        }

        const bool diag = (kb == qt);
        float mxA = -INFINITY, mxB = -INFINITY;
        #pragma unroll
        for (int na = 0; na < 8; na++) {
            float s0 = sacc[na][0] * scale;
            float s1 = sacc[na][1] * scale;
            float s2 = sacc[na][2] * scale;
            float s3 = sacc[na][3] * scale;
            if (diag) {
                int c  = na*8 + 2*tg;
                int rA = m0 + g;
                int rB = rA + 8;
                if (c     > rA) s0 = -INFINITY;
                if (c + 1 > rA) s1 = -INFINITY;
                if (c     > rB) s2 = -INFINITY;
                if (c + 1 > rB) s3 = -INFINITY;
            }
            sacc[na][0] = s0; sacc[na][1] = s1;
            sacc[na][2] = s2; sacc[na][3] = s3;
            mxA = fmaxf(mxA, fmaxf(s0, s1));
            mxB = fmaxf(mxB, fmaxf(s2, s3));
        }
        mxA = fmaxf(mxA, __shfl_xor_sync(0xffffffff, mxA, 1));
        mxA = fmaxf(mxA, __shfl_xor_sync(0xffffffff, mxA, 2));
        mxB = fmaxf(mxB, __shfl_xor_sync(0xffffffff, mxB, 1));
        mxB = fmaxf(mxB, __shfl_xor_sync(0xffffffff, mxB, 2));

        float mnA = fmaxf(mA, mxA);
        float mnB = fmaxf(mB, mxB);
        float cfA = __expf(mA - mnA);
        float cfB = __expf(mB - mnB);
        mA = mnA; mB = mnB;

        float sumA = 0.f, sumB = 0.f;
        uint32_t* prowA = Ps + (m0 + g) * AT_SP;
        uint32_t* prowB = prowA + 8 * AT_SP;
        #pragma unroll
        for (int na = 0; na < 8; na++) {
            int c = na*8 + 2*tg;
            float p0 = __expf(sacc[na][0] - mA);
            float p1 = __expf(sacc[na][1] - mA);
            float p2 = __expf(sacc[na][2] - mB);
            float p3 = __expf(sacc[na][3] - mB);
            sumA += p0 + p1;
            sumB += p2 + p3;
            prowA[c]     = f2tf32(p0);
            prowA[c + 1] = f2tf32(p1);
            prowB[c]     = f2tf32(p2);
            prowB[c + 1] = f2tf32(p3);
        }
        lA = lA * cfA + sumA;
        lB = lB * cfB + sumB;

        #pragma unroll
        for (int na = 0; na < 16; na++) {
            oacc[na][0] *= cfA; oacc[na][1] *= cfA;
            oacc[na][2] *= cfB; oacc[na][3] *= cfB;
        }

        __syncwarp();

        #pragma unroll
        for (int ks = 0; ks < 8; ks++) {
            uint32_t pa0 = Ps[(m0 + g)     * AT_SP + ks*8 + tg];
            uint32_t pa1 = Ps[(m0 + g + 8) * AT_SP + ks*8 + tg];
            uint32_t pa2 = Ps[(m0 + g)     * AT_SP + ks*8 + tg + 4];
            uint32_t pa3 = Ps[(m0 + g + 8) * AT_SP + ks*8 + tg + 4];
            #pragma unroll
            for (int na = 0; na < 16; na++) {
                uint32_t b0 = Vs[(ks*8 + tg)     * AT_SV + na*8 + g];
                uint32_t b1 = Vs[(ks*8 + tg + 4) * AT_SV + na*8 + g];
                mma_tf32(oacc[na][0], oacc[na][1], oacc[na][2], oacc[na][3],
                         pa0, pa1, pa2, pa3, b0, b1);
            }
        }
        __syncthreads();
    }

    lA += __shfl_xor_sync(0xffffffff, lA, 1);
    lA += __shfl_xor_sync(0xffffffff, lA, 2);
    lB += __shfl_xor_sync(0xffffffff, lB, 1);
    lB += __shfl_xor_sync(0xffffffff, lB, 2);
    float invA = 1.f / lA;
    float invB = 1.f / lB;

    float* oA = o + (rowbase + qbase + m0 + g) * (Hh*HDd) + h*HDd;
    float* oB = oA + 8 * (Hh*HDd);
    #pragma unroll
    for (int na = 0; na < 16; na++) {
        int c = na*8 + 2*tg;
        *(float2*)(oA + c) = make_float2(oacc[na][0]*invA, oacc[na][1]*invA);
        *(float2*)(oB + c) = make_float2(oacc[na][2]*invB, oacc[na][3]*invB);
    }
}

// ---------------------------------------------------------------------------
// Launch  (order arranged so the heavy gemm_q is the 4th launch for ncu)
// ---------------------------------------------------------------------------
extern "C" void kernel_launch(void* const* d_in, const int* in_sizes, int n_in,
                              void* d_out, int out_size)
{
    const float* x   = (const float*)d_in[0];
    const float* Wq  = (const float*)d_in[1];
    const float* bq  = (const float*)d_in[2];
    const float* Wkv = (const float*)d_in[3];
    const float* bkv = (const float*)d_in[4];
    const float* Wkr = (const float*)d_in[5];
    const float* bkr = (const float*)d_in[6];
    const float* Wku = (const float*)d_in[7];
    const float* bku = (const float*)d_in[8];
    const float* Wvu = (const float*)d_in[9];
    const float* bvu = (const float*)d_in[10];
    const float* Wo  = (const float*)d_in[11];
    const float* bo  = (const float*)d_in[12];
    float* out = (float*)d_out;

    float *qb, *kvb, *krb, *kcb, *vb, *ob;
    cudaGetSymbolAddress((void**)&qb,  g_q);
    cudaGetSymbolAddress((void**)&kvb, g_kv);
    cudaGetSymbolAddress((void**)&krb, g_kr);
    cudaGetSymbolAddress((void**)&kcb, g_kc);
    cudaGetSymbolAddress((void**)&vb,  g_v);
    cudaGetSymbolAddress((void**)&ob,  g_ao);

    cudaFuncSetAttribute(gemm_tf32,
                         cudaFuncAttributeMaxDynamicSharedMemorySize,
                         GEMM_SMEM_BYTES);
    cudaFuncSetAttribute(attn_mma_kernel,
                         cudaFuncAttributeMaxDynamicSharedMemorySize,
                         AT_SMEM_BYTES);

    const dim3 blk(256);

    // 1-3: kv + kr projections, rope on kr
    gemm_tf32<<<dim3(4, 32), blk, GEMM_SMEM_BYTES>>>(x, Dd, Wkv, bkv, kvb, 2*LATd, Mrows, 2*LATd, Dd);
    gemm_tf32<<<dim3(1, 32), blk, GEMM_SMEM_BYTES>>>(x, Dd, Wkr, bkr, krb, RDd,    Mrows, RDd,    Dd);
    rope_kr_kernel<<<Mrows, 32>>>(krb);

    // 4: the big q projection (ncu target slot)
    gemm_tf32<<<dim3(8, 32), blk, GEMM_SMEM_BYTES>>>(x, Dd, Wq,  bq,  qb,  Hh*HDd, Mrows, Hh*HDd, Dd);

    // 5-7: up-projections, rope on q
    gemm_tf32<<<dim3(4, 32), blk, GEMM_SMEM_BYTES>>>(kvb,        2*LATd, Wku, bku, kcb, Hh*CDd, Mrows, Hh*CDd, LATd);
    gemm_tf32<<<dim3(8, 32), blk, GEMM_SMEM_BYTES>>>(kvb + LATd, 2*LATd, Wvu, bvu, vb,  Hh*HDd, Mrows, Hh*HDd, LATd);
    rope_q_kernel<<<dim3(Mrows, Hh), 32>>>(qb);

    // 8: attention
    attn_mma_kernel<<<dim3(Tt/64, Hh, Bb), dim3(128), AT_SMEM_BYTES>>>(qb, kcb, krb, vb, ob);

    // 9: output projection
    gemm_tf32<<<dim3(8, 32), blk, GEMM_SMEM_BYTES>>>(ob, Hh*HDd, Wo, bo, out, Dd, Mrows, Dd, Dd);
}

// round 7
// speedup vs baseline: 1.2466x; 1.2466x over previous
#include <cuda_runtime.h>
#include <cuda_bf16.h>
#include <math.h>
#include <stdint.h>

// Problem constants
#define Bb   2
#define Tt   2048
#define Dd   2048
#define Hh   16
#define HDd  128
#define LATd 512
#define RDd  64
#define CDd  64
#define Mrows (Bb*Tt)   // 4096

// ---------------------------------------------------------------------------
// Scratch (static device globals; no allocation allowed)
// ---------------------------------------------------------------------------
__device__ float g_q [Mrows * (Hh*HDd)];
__device__ float g_kv[Mrows * (2*LATd)];
__device__ float g_kr[Mrows * RDd];
__device__ float g_kc[Mrows * (Hh*CDd)];
__device__ float g_v [Mrows * (Hh*HDd)];
__device__ float g_ao[Mrows * (Hh*HDd)];

// ---------------------------------------------------------------------------
// Common tf32 helpers (fragment layouts HW-validated rounds 3-6)
// ---------------------------------------------------------------------------
__device__ __forceinline__ uint32_t f2tf32(float f) {
    uint32_t r;
    asm("cvt.rna.tf32.f32 %0, %1;" : "=r"(r) : "f"(f));
    return r;
}

__device__ __forceinline__ void mma_tf32(
    float& c0, float& c1, float& c2, float& c3,
    uint32_t a0, uint32_t a1, uint32_t a2, uint32_t a3,
    uint32_t b0, uint32_t b1)
{
    asm volatile(
        "mma.sync.aligned.m16n8k8.row.col.f32.tf32.tf32.f32 "
        "{%0,%1,%2,%3}, {%4,%5,%6,%7}, {%8,%9}, {%0,%1,%2,%3};\n"
        : "+f"(c0), "+f"(c1), "+f"(c2), "+f"(c3)
        : "r"(a0), "r"(a1), "r"(a2), "r"(a3), "r"(b0), "r"(b1));
}

__device__ __forceinline__ void cp_async16(uint32_t dst_smem, const void* src, int src_bytes) {
    asm volatile("cp.async.cg.shared.global [%0], [%1], 16, %2;\n"
                 :: "r"(dst_smem), "l"(src), "r"(src_bytes));
}
#define CP_COMMIT() asm volatile("cp.async.commit_group;\n" ::: "memory")
#define CP_WAIT1()  asm volatile("cp.async.wait_group 1;\n" ::: "memory")

// ---------------------------------------------------------------------------
// TF32 GEMM (exact round-5 config): C(M,N) = A(M,K) @ W(N,K)^T + bias(N)
// 128x128x32 tiles, 256 threads, warp tile 64x32, cp.async double-buffered.
// ---------------------------------------------------------------------------
#define BM 128
#define BN 128
#define BK 32
#define GST 36
#define G_ASZ (BM*GST)
#define GEMM_SMEM_BYTES (4 * G_ASZ * 4)   // 73728 B

__global__ void __launch_bounds__(256) gemm_tf32(
    const float* __restrict__ A, int lda,
    const float* __restrict__ W,
    const float* __restrict__ bias,
    float* __restrict__ C, int ldc,
    int M, int N, int K)
{
    extern __shared__ float smemf[];
    const uint32_t smem_u32 = (uint32_t)__cvta_generic_to_shared(smemf);

    const int tid  = threadIdx.x;
    const int warp = tid >> 5;
    const int lane = tid & 31;
    const int g    = lane >> 2;
    const int tg   = lane & 3;
    const int wm   = warp & 1;
    const int wn   = warp >> 1;
    const int bm   = blockIdx.y * BM;
    const int bn   = blockIdx.x * BN;
    const int wr0  = wm * 64;
    const int wn0  = wn * 32;

    const int lrow0 = tid >> 3;
    const int lk4   = (tid & 7) * 4;

    float acc[4][4][4];
    #pragma unroll
    for (int mi = 0; mi < 4; mi++)
        #pragma unroll
        for (int ni = 0; ni < 4; ni++)
            #pragma unroll
            for (int r = 0; r < 4; r++) acc[mi][ni][r] = 0.f;

    const int ntiles = K / BK;

    auto prefetch = [&](int k0, int stage) {
        #pragma unroll
        for (int it = 0; it < 4; it++) {
            int row = lrow0 + it * 32;
            uint32_t adst = smem_u32 + (uint32_t)((stage*G_ASZ + row*GST + lk4) * 4);
            cp_async16(adst, A + (size_t)(bm + row) * lda + k0 + lk4, 16);
            int nrow = bn + row;
            uint32_t bdst = smem_u32 + (uint32_t)(((2 + stage)*G_ASZ + row*GST + lk4) * 4);
            cp_async16(bdst, W + (size_t)(nrow < N ? nrow : 0) * K + k0 + lk4,
                       nrow < N ? 16 : 0);
        }
    };

    prefetch(0, 0);
    CP_COMMIT();

    for (int t = 0; t < ntiles; t++) {
        if (t + 1 < ntiles) prefetch((t + 1) * BK, (t + 1) & 1);
        CP_COMMIT();
        CP_WAIT1();
        __syncthreads();

        const float* Asb = smemf + (t & 1) * G_ASZ;
        const float* Bsb = smemf + (2 + (t & 1)) * G_ASZ;

        #pragma unroll
        for (int kk = 0; kk < BK; kk += 8) {
            uint32_t af[4][4], bf[4][2];
            #pragma unroll
            for (int mi = 0; mi < 4; mi++) {
                int r0 = wr0 + mi * 16 + g;
                af[mi][0] = f2tf32(Asb[r0*GST       + kk + tg]);
                af[mi][1] = f2tf32(Asb[(r0+8)*GST   + kk + tg]);
                af[mi][2] = f2tf32(Asb[r0*GST       + kk + tg + 4]);
                af[mi][3] = f2tf32(Asb[(r0+8)*GST   + kk + tg + 4]);
            }
            #pragma unroll
            for (int ni = 0; ni < 4; ni++) {
                int n0 = wn0 + ni * 8 + g;
                bf[ni][0] = f2tf32(Bsb[n0*GST + kk + tg]);
                bf[ni][1] = f2tf32(Bsb[n0*GST + kk + tg + 4]);
            }
            #pragma unroll
            for (int mi = 0; mi < 4; mi++)
                #pragma unroll
                for (int ni = 0; ni < 4; ni++)
                    mma_tf32(acc[mi][ni][0], acc[mi][ni][1],
                             acc[mi][ni][2], acc[mi][ni][3],
                             af[mi][0], af[mi][1], af[mi][2], af[mi][3],
                             bf[ni][0], bf[ni][1]);
        }
        __syncthreads();
    }

    #pragma unroll
    for (int mi = 0; mi < 4; mi++) {
        int row0 = bm + wr0 + mi * 16 + g;
        #pragma unroll
        for (int ni = 0; ni < 4; ni++) {
            int col = bn + wn0 + ni * 8 + 2 * tg;
            if (col < N) {
                float b0 = bias[col];
                float b1 = bias[col + 1];
                float* p0 = C + (size_t)row0 * ldc + col;
                float* p1 = C + (size_t)(row0 + 8) * ldc + col;
                p0[0] = acc[mi][ni][0] + b0;
                p0[1] = acc[mi][ni][1] + b1;
                p1[0] = acc[mi][ni][2] + b0;
                p1[1] = acc[mi][ni][3] + b1;
            }
        }
    }
}

// ---------------------------------------------------------------------------
// RoPE (rotate-half). RD=64, half=32.
// ---------------------------------------------------------------------------
__device__ __forceinline__ void rope_pair(float* p, int i, int t)
{
    float inv_freq = powf(10000.f, -(float)i / 32.f);
    float ang = (float)t * inv_freq;
    float s, c;
    sincosf(ang, &s, &c);
    float x1 = p[i];
    float x2 = p[i + 32];
    p[i]      = x1 * c - x2 * s;
    p[i + 32] = x2 * c + x1 * s;
}

__global__ void rope_kr_kernel(float* __restrict__ kr)
{
    int row = blockIdx.x;
    int t   = row & (Tt - 1);
    rope_pair(kr + (size_t)row * RDd, threadIdx.x, t);
}

__global__ void rope_q_kernel(float* __restrict__ qb)
{
    int row = blockIdx.x;
    int h   = blockIdx.y;
    int t   = row & (Tt - 1);
    rope_pair(qb + (size_t)row * (Hh*HDd) + h*HDd + CDd, threadIdx.x, t);
}

// ---------------------------------------------------------------------------
// Tensor-core flash attention, 128-row q blocks, cp.async double-buffered K/V.
// 256 threads (8 warps), each warp owns 16 q-rows end-to-end.
// K/V tiles (64 rows) shared by all 128 q rows -> half the smem traffic/syncs.
// K/V stored raw fp32 (cp.async), tf32 cvt at fragment load (identical bits).
// smem: Ks 2x64x132 + Vs 2x64x136 + Ps 128x68 = 43008 floats = 168 KB.
// ---------------------------------------------------------------------------
#define A2_SK 132
#define A2_SV 136
#define A2_SP 68
#define A2_KSZ (64*A2_SK)
#define A2_VSZ (64*A2_SV)
#define A2_SMEM_BYTES ((2*A2_KSZ + 2*A2_VSZ + 128*A2_SP) * 4)

__global__ void __launch_bounds__(256, 1) attn_mma_kernel(
    const float* __restrict__ q,
    const float* __restrict__ kc,
    const float* __restrict__ kr,
    const float* __restrict__ v,
    float* __restrict__ o)
{
    extern __shared__ float smf[];
    float*    Ksf = smf;                       // 2 stages x 64 x A2_SK
    float*    Vsf = smf + 2*A2_KSZ;            // 2 stages x 64 x A2_SV
    uint32_t* Ps  = (uint32_t*)(smf + 2*A2_KSZ + 2*A2_VSZ);   // 128 x A2_SP (tf32)
    const uint32_t smem_u32 = (uint32_t)__cvta_generic_to_shared(smf);

    const int qt   = (Tt/128 - 1) - blockIdx.x;   // heavy q-blocks first
    const int h    = blockIdx.y;
    const int b    = blockIdx.z;
    const int tid  = threadIdx.x;
    const int warp = tid >> 5;
    const int lane = tid & 31;
    const int g    = lane >> 2;
    const int tg   = lane & 3;
    const int m0   = warp * 16;                   // warp's q-row offset (0..112)
    const int qbase = qt * 128;
    const size_t rowbase = (size_t)b * Tt;
    const float scale = 0.08838834764831845f;     // 1/sqrt(128)

    // ---- Q fragments in registers: rows m0+g / m0+g+8, 16 k-steps ----
    uint32_t aq[16][4];
    {
        const float* qA = q + (rowbase + qbase + m0 + g) * (Hh*HDd) + h*HDd;
        const float* qB = qA + 8 * (Hh*HDd);
        #pragma unroll
        for (int ks = 0; ks < 16; ks++) {
            int k0 = ks * 8;
            aq[ks][0] = f2tf32(qA[k0 + tg]);
            aq[ks][1] = f2tf32(qB[k0 + tg]);
            aq[ks][2] = f2tf32(qA[k0 + tg + 4]);
            aq[ks][3] = f2tf32(qB[k0 + tg + 4]);
        }
    }

    float oacc[16][4];
    #pragma unroll
    for (int na = 0; na < 16; na++)
        #pragma unroll
        for (int r = 0; r < 4; r++) oacc[na][r] = 0.f;

    float mA = -INFINITY, mB = -INFINITY;
    float lA = 0.f, lB = 0.f;

    const int rAg = qbase + m0 + g;      // this thread's two global q rows
    const int rBg = rAg + 8;
    const int ntiles = 2*qt + 2;         // last k tile covers qbase+64..qbase+127

    // cp.async prefetch of one 64-row K/V tile into stage s
    auto prefetch = [&](int kb, int s) {
        const int kbase = kb * 64;
        // 64 rows x 32 float4 = 2048 chunks for K and for V; 8 each per thread
        #pragma unroll
        for (int it = 0; it < 8; it++) {
            int i  = tid + it * 256;
            int rr = i >> 5;
            int c4 = i & 31;
            size_t trow = rowbase + kbase + rr;
            const float* ksrc = (c4 < 16)
                ? (kc + trow * (Hh*CDd) + h*CDd + c4*4)
                : (kr + trow * RDd + (c4-16)*4);
            uint32_t kdst = smem_u32 + (uint32_t)((s*A2_KSZ + rr*A2_SK + c4*4) * 4);
            cp_async16(kdst, ksrc, 16);
            const float* vsrc = v + trow * (Hh*HDd) + h*HDd + c4*4;
            uint32_t vdst = smem_u32 + (uint32_t)((2*A2_KSZ + s*A2_VSZ + rr*A2_SV + c4*4) * 4);
            cp_async16(vdst, vsrc, 16);
        }
    };

    prefetch(0, 0);
    CP_COMMIT();

    for (int kb = 0; kb < ntiles; kb++) {
        if (kb + 1 < ntiles) prefetch(kb + 1, (kb + 1) & 1);
        CP_COMMIT();
        CP_WAIT1();
        __syncthreads();

        const int kbase = kb * 64;
        const float* Kst = Ksf + (kb & 1) * A2_KSZ;
        const float* Vst = Vsf + (kb & 1) * A2_VSZ;

        // warp-level skip: tile entirely above-diagonal for this warp's rows
        const bool active = (kbase <= qbase + m0 + 15);
        if (active) {
            // ---- S = Q @ K^T ----
            float sacc[8][4];
            #pragma unroll
            for (int na = 0; na < 8; na++)
                #pragma unroll
                for (int r = 0; r < 4; r++) sacc[na][r] = 0.f;

            #pragma unroll
            for (int ks = 0; ks < 16; ks++) {
                #pragma unroll
                for (int na = 0; na < 8; na++) {
                    uint32_t b0 = f2tf32(Kst[(na*8 + g)*A2_SK + ks*8 + tg]);
                    uint32_t b1 = f2tf32(Kst[(na*8 + g)*A2_SK + ks*8 + tg + 4]);
                    mma_tf32(sacc[na][0], sacc[na][1], sacc[na][2], sacc[na][3],
                             aq[ks][0], aq[ks][1], aq[ks][2], aq[ks][3], b0, b1);
                }
            }

            // ---- scale + causal mask + row max ----
            const bool needmask = (kbase + 63 > rAg);   // tile crosses a diagonal
            float mxA = -INFINITY, mxB = -INFINITY;
            #pragma unroll
            for (int na = 0; na < 8; na++) {
                float s0 = sacc[na][0] * scale;
                float s1 = sacc[na][1] * scale;
                float s2 = sacc[na][2] * scale;
                float s3 = sacc[na][3] * scale;
                if (needmask) {
                    int cg = kbase + na*8 + 2*tg;
                    if (cg     > rAg) s0 = -INFINITY;
                    if (cg + 1 > rAg) s1 = -INFINITY;
                    if (cg     > rBg) s2 = -INFINITY;
                    if (cg + 1 > rBg) s3 = -INFINITY;
                }
                sacc[na][0] = s0; sacc[na][1] = s1;
                sacc[na][2] = s2; sacc[na][3] = s3;
                mxA = fmaxf(mxA, fmaxf(s0, s1));
                mxB = fmaxf(mxB, fmaxf(s2, s3));
            }
            mxA = fmaxf(mxA, __shfl_xor_sync(0xffffffff, mxA, 1));
            mxA = fmaxf(mxA, __shfl_xor_sync(0xffffffff, mxA, 2));
            mxB = fmaxf(mxB, __shfl_xor_sync(0xffffffff, mxB, 1));
            mxB = fmaxf(mxB, __shfl_xor_sync(0xffffffff, mxB, 2));

            float mnA = fmaxf(mA, mxA);
            float mnB = fmaxf(mB, mxB);
            float cfA = __expf(mA - mnA);
            float cfB = __expf(mB - mnB);
            mA = mnA; mB = mnB;

            // ---- p = exp(s-m) -> Ps (tf32); partial row sums ----
            float sumA = 0.f, sumB = 0.f;
            uint32_t* prowA = Ps + (m0 + g) * A2_SP;
            uint32_t* prowB = prowA + 8 * A2_SP;
            #pragma unroll
            for (int na = 0; na < 8; na++) {
                int c = na*8 + 2*tg;
                float p0 = __expf(sacc[na][0] - mA);
                float p1 = __expf(sacc[na][1] - mA);
                float p2 = __expf(sacc[na][2] - mB);
                float p3 = __expf(sacc[na][3] - mB);
                sumA += p0 + p1;
                sumB += p2 + p3;
                prowA[c]     = f2tf32(p0);
                prowA[c + 1] = f2tf32(p1);
                prowB[c]     = f2tf32(p2);
                prowB[c + 1] = f2tf32(p3);
            }
            lA = lA * cfA + sumA;
            lB = lB * cfB + sumB;

            #pragma unroll
            for (int na = 0; na < 16; na++) {
                oacc[na][0] *= cfA; oacc[na][1] *= cfA;
                oacc[na][2] *= cfB; oacc[na][3] *= cfB;
            }

            __syncwarp();   // P rows warp-private: order STS before LDS

            // ---- O += P @ V ----
            #pragma unroll
            for (int ks = 0; ks < 8; ks++) {
                uint32_t pa0 = Ps[(m0 + g)     * A2_SP + ks*8 + tg];
                uint32_t pa1 = Ps[(m0 + g + 8) * A2_SP + ks*8 + tg];
                uint32_t pa2 = Ps[(m0 + g)     * A2_SP + ks*8 + tg + 4];
                uint32_t pa3 = Ps[(m0 + g + 8) * A2_SP + ks*8 + tg + 4];
                #pragma unroll
                for (int na = 0; na < 16; na++) {
                    uint32_t b0 = f2tf32(Vst[(ks*8 + tg)     * A2_SV + na*8 + g]);
                    uint32_t b1 = f2tf32(Vst[(ks*8 + tg + 4) * A2_SV + na*8 + g]);
                    mma_tf32(oacc[na][0], oacc[na][1], oacc[na][2], oacc[na][3],
                             pa0, pa1, pa2, pa3, b0, b1);
                }
            }
        }
        __syncthreads();   // all warps done with this stage before overwrite
    }

    lA += __shfl_xor_sync(0xffffffff, lA, 1);
    lA += __shfl_xor_sync(0xffffffff, lA, 2);
    lB += __shfl_xor_sync(0xffffffff, lB, 1);
    lB += __shfl_xor_sync(0xffffffff, lB, 2);
    float invA = 1.f / lA;
    float invB = 1.f / lB;

    float* oA = o + (rowbase + qbase + m0 + g) * (Hh*HDd) + h*HDd;
    float* oB = oA + 8 * (Hh*HDd);
    #pragma unroll
    for (int na = 0; na < 16; na++) {
        int c = na*8 + 2*tg;
        *(float2*)(oA + c) = make_float2(oacc[na][0]*invA, oacc[na][1]*invA);
        *(float2*)(oB + c) = make_float2(oacc[na][2]*invB, oacc[na][3]*invB);
    }
}

// ---------------------------------------------------------------------------
// Launch  (gemm_q kept in slot 4 for ncu)
// ---------------------------------------------------------------------------
extern "C" void kernel_launch(void* const* d_in, const int* in_sizes, int n_in,
                              void* d_out, int out_size)
{
    const float* x   = (const float*)d_in[0];
    const float* Wq  = (const float*)d_in[1];
    const float* bq  = (const float*)d_in[2];
    const float* Wkv = (const float*)d_in[3];
    const float* bkv = (const float*)d_in[4];
    const float* Wkr = (const float*)d_in[5];
    const float* bkr = (const float*)d_in[6];
    const float* Wku = (const float*)d_in[7];
    const float* bku = (const float*)d_in[8];
    const float* Wvu = (const float*)d_in[9];
    const float* bvu = (const float*)d_in[10];
    const float* Wo  = (const float*)d_in[11];
    const float* bo  = (const float*)d_in[12];
    float* out = (float*)d_out;

    float *qb, *kvb, *krb, *kcb, *vb, *ob;
    cudaGetSymbolAddress((void**)&qb,  g_q);
    cudaGetSymbolAddress((void**)&kvb, g_kv);
    cudaGetSymbolAddress((void**)&krb, g_kr);
    cudaGetSymbolAddress((void**)&kcb, g_kc);
    cudaGetSymbolAddress((void**)&vb,  g_v);
    cudaGetSymbolAddress((void**)&ob,  g_ao);

    cudaFuncSetAttribute(gemm_tf32,
                         cudaFuncAttributeMaxDynamicSharedMemorySize,
                         GEMM_SMEM_BYTES);
    cudaFuncSetAttribute(attn_mma_kernel,
                         cudaFuncAttributeMaxDynamicSharedMemorySize,
                         A2_SMEM_BYTES);

    const dim3 blk(256);

    // 1-3: kv + kr projections, rope on kr
    gemm_tf32<<<dim3(8, 32), blk, GEMM_SMEM_BYTES>>>(x, Dd, Wkv, bkv, kvb, 2*LATd, Mrows, 2*LATd, Dd);
    gemm_tf32<<<dim3(1, 32), blk, GEMM_SMEM_BYTES>>>(x, Dd, Wkr, bkr, krb, RDd,    Mrows, RDd,    Dd);
    rope_kr_kernel<<<Mrows, 32>>>(krb);

    // 4: the big q projection (ncu target slot)
    gemm_tf32<<<dim3(16, 32), blk, GEMM_SMEM_BYTES>>>(x, Dd, Wq,  bq,  qb,  Hh*HDd, Mrows, Hh*HDd, Dd);

    // 5-7: up-projections, rope on q
    gemm_tf32<<<dim3(8,  32), blk, GEMM_SMEM_BYTES>>>(kvb,        2*LATd, Wku, bku, kcb, Hh*CDd, Mrows, Hh*CDd, LATd);
    gemm_tf32<<<dim3(16, 32), blk, GEMM_SMEM_BYTES>>>(kvb + LATd, 2*LATd, Wvu, bvu, vb,  Hh*HDd, Mrows, Hh*HDd, LATd);
    rope_q_kernel<<<dim3(Mrows, Hh), 32>>>(qb);

    // 8: attention (128-row q blocks)
    attn_mma_kernel<<<dim3(Tt/128, Hh, Bb), blk, A2_SMEM_BYTES>>>(qb, kcb, krb, vb, ob);

    // 9: output projection
    gemm_tf32<<<dim3(16, 32), blk, GEMM_SMEM_BYTES>>>(ob, Hh*HDd, Wo, bo, out, Dd, Mrows, Dd, Dd);
}

// round 9
// speedup vs baseline: 1.3456x; 1.0794x over previous
#include <cuda_runtime.h>
#include <cuda_bf16.h>
#include <math.h>
#include <stdint.h>

// Problem constants
#define Bb   2
#define Tt   2048
#define Dd   2048
#define Hh   16
#define HDd  128
#define LATd 512
#define RDd  64
#define CDd  64
#define Mrows (Bb*Tt)   // 4096

// ---------------------------------------------------------------------------
// Scratch (static device globals; no allocation allowed)
// ---------------------------------------------------------------------------
__device__ float g_q [Mrows * (Hh*HDd)];
__device__ float g_kv[Mrows * (2*LATd)];
__device__ float g_kr[Mrows * RDd];
__device__ float g_kc[Mrows * (Hh*CDd)];
__device__ float g_v [Mrows * (Hh*HDd)];
__device__ float g_ao[Mrows * (Hh*HDd)];

// ---------------------------------------------------------------------------
// Common tf32 helpers (fragment layouts HW-validated rounds 3-7)
// ---------------------------------------------------------------------------
__device__ __forceinline__ uint32_t f2tf32(float f) {
    uint32_t r;
    asm("cvt.rna.tf32.f32 %0, %1;" : "=r"(r) : "f"(f));
    return r;
}

__device__ __forceinline__ void mma_tf32(
    float& c0, float& c1, float& c2, float& c3,
    uint32_t a0, uint32_t a1, uint32_t a2, uint32_t a3,
    uint32_t b0, uint32_t b1)
{
    asm volatile(
        "mma.sync.aligned.m16n8k8.row.col.f32.tf32.tf32.f32 "
        "{%0,%1,%2,%3}, {%4,%5,%6,%7}, {%8,%9}, {%0,%1,%2,%3};\n"
        : "+f"(c0), "+f"(c1), "+f"(c2), "+f"(c3)
        : "r"(a0), "r"(a1), "r"(a2), "r"(a3), "r"(b0), "r"(b1));
}

__device__ __forceinline__ void cp_async16(uint32_t dst_smem, const void* src, int src_bytes) {
    asm volatile("cp.async.cg.shared.global [%0], [%1], 16, %2;\n"
                 :: "r"(dst_smem), "l"(src), "r"(src_bytes));
}
#define CP_COMMIT() asm volatile("cp.async.commit_group;\n" ::: "memory")
#define CP_WAIT1()  asm volatile("cp.async.wait_group 1;\n" ::: "memory")

// ---------------------------------------------------------------------------
// TF32 GEMM: C(M,N) = A(M,K) @ W(N,K)^T + bias(N)
// 128x128x32 tiles, 256 threads, warp tile 64x32, cp.async double-buffered.
// __launch_bounds__(256, 2): cap regs at 128 so 2 CTAs/SM fit (R7: 132 regs
// left us register-limited to 1 CTA/SM, occ 12.5%, tensor pipe 39%).
// ---------------------------------------------------------------------------
#define BM 128
#define BN 128
#define BK 32
#define GST 36
#define G_ASZ (BM*GST)
#define GEMM_SMEM_BYTES (4 * G_ASZ * 4)   // 73728 B

__global__ void __launch_bounds__(256, 2) gemm_tf32(
    const float* __restrict__ A, int lda,
    const float* __restrict__ W,
    const float* __restrict__ bias,
    float* __restrict__ C, int ldc,
    int M, int N, int K)
{
    extern __shared__ float smemf[];
    const uint32_t smem_u32 = (uint32_t)__cvta_generic_to_shared(smemf);

    const int tid  = threadIdx.x;
    const int warp = tid >> 5;
    const int lane = tid & 31;
    const int g    = lane >> 2;
    const int tg   = lane & 3;
    const int wm   = warp & 1;
    const int wn   = warp >> 1;
    const int bm   = blockIdx.y * BM;
    const int bn   = blockIdx.x * BN;
    const int wr0  = wm * 64;
    const int wn0  = wn * 32;

    const int lrow0 = tid >> 3;
    const int lk4   = (tid & 7) * 4;

    float acc[4][4][4];
    #pragma unroll
    for (int mi = 0; mi < 4; mi++)
        #pragma unroll
        for (int ni = 0; ni < 4; ni++)
            #pragma unroll
            for (int r = 0; r < 4; r++) acc[mi][ni][r] = 0.f;

    const int ntiles = K / BK;

    auto prefetch = [&](int k0, int stage) {
        #pragma unroll
        for (int it = 0; it < 4; it++) {
            int row = lrow0 + it * 32;
            uint32_t adst = smem_u32 + (uint32_t)((stage*G_ASZ + row*GST + lk4) * 4);
            cp_async16(adst, A + (size_t)(bm + row) * lda + k0 + lk4, 16);
            int nrow = bn + row;
            uint32_t bdst = smem_u32 + (uint32_t)(((2 + stage)*G_ASZ + row*GST + lk4) * 4);
            cp_async16(bdst, W + (size_t)(nrow < N ? nrow : 0) * K + k0 + lk4,
                       nrow < N ? 16 : 0);
        }
    };

    prefetch(0, 0);
    CP_COMMIT();

    for (int t = 0; t < ntiles; t++) {
        if (t + 1 < ntiles) prefetch((t + 1) * BK, (t + 1) & 1);
        CP_COMMIT();
        CP_WAIT1();
        __syncthreads();

        const float* Asb = smemf + (t & 1) * G_ASZ;
        const float* Bsb = smemf + (2 + (t & 1)) * G_ASZ;

        #pragma unroll
        for (int kk = 0; kk < BK; kk += 8) {
            uint32_t af[4][4], bf[4][2];
            #pragma unroll
            for (int mi = 0; mi < 4; mi++) {
                int r0 = wr0 + mi * 16 + g;
                af[mi][0] = f2tf32(Asb[r0*GST       + kk + tg]);
                af[mi][1] = f2tf32(Asb[(r0+8)*GST   + kk + tg]);
                af[mi][2] = f2tf32(Asb[r0*GST       + kk + tg + 4]);
                af[mi][3] = f2tf32(Asb[(r0+8)*GST   + kk + tg + 4]);
            }
            #pragma unroll
            for (int ni = 0; ni < 4; ni++) {
                int n0 = wn0 + ni * 8 + g;
                bf[ni][0] = f2tf32(Bsb[n0*GST + kk + tg]);
                bf[ni][1] = f2tf32(Bsb[n0*GST + kk + tg + 4]);
            }
            #pragma unroll
            for (int mi = 0; mi < 4; mi++)
                #pragma unroll
                for (int ni = 0; ni < 4; ni++)
                    mma_tf32(acc[mi][ni][0], acc[mi][ni][1],
                             acc[mi][ni][2], acc[mi][ni][3],
                             af[mi][0], af[mi][1], af[mi][2], af[mi][3],
                             bf[ni][0], bf[ni][1]);
        }
        __syncthreads();
    }

    #pragma unroll
    for (int mi = 0; mi < 4; mi++) {
        int row0 = bm + wr0 + mi * 16 + g;
        #pragma unroll
        for (int ni = 0; ni < 4; ni++) {
            int col = bn + wn0 + ni * 8 + 2 * tg;
            if (col < N) {
                float b0 = bias[col];
                float b1 = bias[col + 1];
                float* p0 = C + (size_t)row0 * ldc + col;
                float* p1 = C + (size_t)(row0 + 8) * ldc + col;
                p0[0] = acc[mi][ni][0] + b0;
                p0[1] = acc[mi][ni][1] + b1;
                p1[0] = acc[mi][ni][2] + b0;
                p1[1] = acc[mi][ni][3] + b1;
            }
        }
    }
}

// ---------------------------------------------------------------------------
// RoPE (rotate-half). RD=64, half=32.
// ---------------------------------------------------------------------------
__device__ __forceinline__ void rope_pair(float* p, int i, int t)
{
    float inv_freq = powf(10000.f, -(float)i / 32.f);
    float ang = (float)t * inv_freq;
    float s, c;
    sincosf(ang, &s, &c);
    float x1 = p[i];
    float x2 = p[i + 32];
    p[i]      = x1 * c - x2 * s;
    p[i + 32] = x2 * c + x1 * s;
}

__global__ void rope_kr_kernel(float* __restrict__ kr)
{
    int row = blockIdx.x;
    int t   = row & (Tt - 1);
    rope_pair(kr + (size_t)row * RDd, threadIdx.x, t);
}

__global__ void rope_q_kernel(float* __restrict__ qb)
{
    int row = blockIdx.x;
    int h   = blockIdx.y;
    int t   = row & (Tt - 1);
    rope_pair(qb + (size_t)row * (Hh*HDd) + h*HDd + CDd, threadIdx.x, t);
}

// ---------------------------------------------------------------------------
// Tensor-core flash attention, 128-row q blocks, cp.async double-buffered K/V.
// (unchanged from round 7)
// ---------------------------------------------------------------------------
#define A2_SK 132
#define A2_SV 136
#define A2_SP 68
#define A2_KSZ (64*A2_SK)
#define A2_VSZ (64*A2_SV)
#define A2_SMEM_BYTES ((2*A2_KSZ + 2*A2_VSZ + 128*A2_SP) * 4)

__global__ void __launch_bounds__(256, 1) attn_mma_kernel(
    const float* __restrict__ q,
    const float* __restrict__ kc,
    const float* __restrict__ kr,
    const float* __restrict__ v,
    float* __restrict__ o)
{
    extern __shared__ float smf[];
    float*    Ksf = smf;
    float*    Vsf = smf + 2*A2_KSZ;
    uint32_t* Ps  = (uint32_t*)(smf + 2*A2_KSZ + 2*A2_VSZ);
    const uint32_t smem_u32 = (uint32_t)__cvta_generic_to_shared(smf);

    const int qt   = (Tt/128 - 1) - blockIdx.x;
    const int h    = blockIdx.y;
    const int b    = blockIdx.z;
    const int tid  = threadIdx.x;
    const int warp = tid >> 5;
    const int lane = tid & 31;
    const int g    = lane >> 2;
    const int tg   = lane & 3;
    const int m0   = warp * 16;
    const int qbase = qt * 128;
    const size_t rowbase = (size_t)b * Tt;
    const float scale = 0.08838834764831845f;

    uint32_t aq[16][4];
    {
        const float* qA = q + (rowbase + qbase + m0 + g) * (Hh*HDd) + h*HDd;
        const float* qB = qA + 8 * (Hh*HDd);
        #pragma unroll
        for (int ks = 0; ks < 16; ks++) {
            int k0 = ks * 8;
            aq[ks][0] = f2tf32(qA[k0 + tg]);
            aq[ks][1] = f2tf32(qB[k0 + tg]);
            aq[ks][2] = f2tf32(qA[k0 + tg + 4]);
            aq[ks][3] = f2tf32(qB[k0 + tg + 4]);
        }
    }

    float oacc[16][4];
    #pragma unroll
    for (int na = 0; na < 16; na++)
        #pragma unroll
        for (int r = 0; r < 4; r++) oacc[na][r] = 0.f;

    float mA = -INFINITY, mB = -INFINITY;
    float lA = 0.f, lB = 0.f;

    const int rAg = qbase + m0 + g;
    const int rBg = rAg + 8;
    const int ntiles = 2*qt + 2;

    auto prefetch = [&](int kb, int s) {
        const int kbase = kb * 64;
        #pragma unroll
        for (int it = 0; it < 8; it++) {
            int i  = tid + it * 256;
            int rr = i >> 5;
            int c4 = i & 31;
            size_t trow = rowbase + kbase + rr;
            const float* ksrc = (c4 < 16)
                ? (kc + trow * (Hh*CDd) + h*CDd + c4*4)
                : (kr + trow * RDd + (c4-16)*4);
            uint32_t kdst = smem_u32 + (uint32_t)((s*A2_KSZ + rr*A2_SK + c4*4) * 4);
            cp_async16(kdst, ksrc, 16);
            const float* vsrc = v + trow * (Hh*HDd) + h*HDd + c4*4;
            uint32_t vdst = smem_u32 + (uint32_t)((2*A2_KSZ + s*A2_VSZ + rr*A2_SV + c4*4) * 4);
            cp_async16(vdst, vsrc, 16);
        }
    };

    prefetch(0, 0);
    CP_COMMIT();

    for (int kb = 0; kb < ntiles; kb++) {
        if (kb + 1 < ntiles) prefetch(kb + 1, (kb + 1) & 1);
        CP_COMMIT();
        CP_WAIT1();
        __syncthreads();

        const int kbase = kb * 64;
        const float* Kst = Ksf + (kb & 1) * A2_KSZ;
        const float* Vst = Vsf + (kb & 1) * A2_VSZ;

        const bool active = (kbase <= qbase + m0 + 15);
        if (active) {
            float sacc[8][4];
            #pragma unroll
            for (int na = 0; na < 8; na++)
                #pragma unroll
                for (int r = 0; r < 4; r++) sacc[na][r] = 0.f;

            #pragma unroll
            for (int ks = 0; ks < 16; ks++) {
                #pragma unroll
                for (int na = 0; na < 8; na++) {
                    uint32_t b0 = f2tf32(Kst[(na*8 + g)*A2_SK + ks*8 + tg]);
                    uint32_t b1 = f2tf32(Kst[(na*8 + g)*A2_SK + ks*8 + tg + 4]);
                    mma_tf32(sacc[na][0], sacc[na][1], sacc[na][2], sacc[na][3],
                             aq[ks][0], aq[ks][1], aq[ks][2], aq[ks][3], b0, b1);
                }
            }

            const bool needmask = (kbase + 63 > rAg);
            float mxA = -INFINITY, mxB = -INFINITY;
            #pragma unroll
            for (int na = 0; na < 8; na++) {
                float s0 = sacc[na][0] * scale;
                float s1 = sacc[na][1] * scale;
                float s2 = sacc[na][2] * scale;
                float s3 = sacc[na][3] * scale;
                if (needmask) {
                    int cg = kbase + na*8 + 2*tg;
                    if (cg     > rAg) s0 = -INFINITY;
                    if (cg + 1 > rAg) s1 = -INFINITY;
                    if (cg     > rBg) s2 = -INFINITY;
                    if (cg + 1 > rBg) s3 = -INFINITY;
                }
                sacc[na][0] = s0; sacc[na][1] = s1;
                sacc[na][2] = s2; sacc[na][3] = s3;
                mxA = fmaxf(mxA, fmaxf(s0, s1));
                mxB = fmaxf(mxB, fmaxf(s2, s3));
            }
            mxA = fmaxf(mxA, __shfl_xor_sync(0xffffffff, mxA, 1));
            mxA = fmaxf(mxA, __shfl_xor_sync(0xffffffff, mxA, 2));
            mxB = fmaxf(mxB, __shfl_xor_sync(0xffffffff, mxB, 1));
            mxB = fmaxf(mxB, __shfl_xor_sync(0xffffffff, mxB, 2));

            float mnA = fmaxf(mA, mxA);
            float mnB = fmaxf(mB, mxB);
            float cfA = __expf(mA - mnA);
            float cfB = __expf(mB - mnB);
            mA = mnA; mB = mnB;

            float sumA = 0.f, sumB = 0.f;
            uint32_t* prowA = Ps + (m0 + g) * A2_SP;
            uint32_t* prowB = prowA + 8 * A2_SP;
            #pragma unroll
            for (int na = 0; na < 8; na++) {
                int c = na*8 + 2*tg;
                float p0 = __expf(sacc[na][0] - mA);
                float p1 = __expf(sacc[na][1] - mA);
                float p2 = __expf(sacc[na][2] - mB);
                float p3 = __expf(sacc[na][3] - mB);
                sumA += p0 + p1;
                sumB += p2 + p3;
                prowA[c]     = f2tf32(p0);
                prowA[c + 1] = f2tf32(p1);
                prowB[c]     = f2tf32(p2);
                prowB[c + 1] = f2tf32(p3);
            }
            lA = lA * cfA + sumA;
            lB = lB * cfB + sumB;

            #pragma unroll
            for (int na = 0; na < 16; na++) {
                oacc[na][0] *= cfA; oacc[na][1] *= cfA;
                oacc[na][2] *= cfB; oacc[na][3] *= cfB;
            }

            __syncwarp();

            #pragma unroll
            for (int ks = 0; ks < 8; ks++) {
                uint32_t pa0 = Ps[(m0 + g)     * A2_SP + ks*8 + tg];
                uint32_t pa1 = Ps[(m0 + g + 8) * A2_SP + ks*8 + tg];
                uint32_t pa2 = Ps[(m0 + g)     * A2_SP + ks*8 + tg + 4];
                uint32_t pa3 = Ps[(m0 + g + 8) * A2_SP + ks*8 + tg + 4];
                #pragma unroll
                for (int na = 0; na < 16; na++) {
                    uint32_t b0 = f2tf32(Vst[(ks*8 + tg)     * A2_SV + na*8 + g]);
                    uint32_t b1 = f2tf32(Vst[(ks*8 + tg + 4) * A2_SV + na*8 + g]);
                    mma_tf32(oacc[na][0], oacc[na][1], oacc[na][2], oacc[na][3],
                             pa0, pa1, pa2, pa3, b0, b1);
                }
            }
        }
        __syncthreads();
    }

    lA += __shfl_xor_sync(0xffffffff, lA, 1);
    lA += __shfl_xor_sync(0xffffffff, lA, 2);
    lB += __shfl_xor_sync(0xffffffff, lB, 1);
    lB += __shfl_xor_sync(0xffffffff, lB, 2);
    float invA = 1.f / lA;
    float invB = 1.f / lB;

    float* oA = o + (rowbase + qbase + m0 + g) * (Hh*HDd) + h*HDd;
    float* oB = oA + 8 * (Hh*HDd);
    #pragma unroll
    for (int na = 0; na < 16; na++) {
        int c = na*8 + 2*tg;
        *(float2*)(oA + c) = make_float2(oacc[na][0]*invA, oacc[na][1]*invA);
        *(float2*)(oB + c) = make_float2(oacc[na][2]*invB, oacc[na][3]*invB);
    }
}

// ---------------------------------------------------------------------------
// Launch  (gemm_q kept in slot 4 for ncu)
// ---------------------------------------------------------------------------
extern "C" void kernel_launch(void* const* d_in, const int* in_sizes, int n_in,
                              void* d_out, int out_size)
{
    const float* x   = (const float*)d_in[0];
    const float* Wq  = (const float*)d_in[1];
    const float* bq  = (const float*)d_in[2];
    const float* Wkv = (const float*)d_in[3];
    const float* bkv = (const float*)d_in[4];
    const float* Wkr = (const float*)d_in[5];
    const float* bkr = (const float*)d_in[6];
    const float* Wku = (const float*)d_in[7];
    const float* bku = (const float*)d_in[8];
    const float* Wvu = (const float*)d_in[9];
    const float* bvu = (const float*)d_in[10];
    const float* Wo  = (const float*)d_in[11];
    const float* bo  = (const float*)d_in[12];
    float* out = (float*)d_out;

    float *qb, *kvb, *krb, *kcb, *vb, *ob;
    cudaGetSymbolAddress((void**)&qb,  g_q);
    cudaGetSymbolAddress((void**)&kvb, g_kv);
    cudaGetSymbolAddress((void**)&krb, g_kr);
    cudaGetSymbolAddress((void**)&kcb, g_kc);
    cudaGetSymbolAddress((void**)&vb,  g_v);
    cudaGetSymbolAddress((void**)&ob,  g_ao);

    cudaFuncSetAttribute(gemm_tf32,
                         cudaFuncAttributeMaxDynamicSharedMemorySize,
                         GEMM_SMEM_BYTES);
    cudaFuncSetAttribute(attn_mma_kernel,
                         cudaFuncAttributeMaxDynamicSharedMemorySize,
                         A2_SMEM_BYTES);

    const dim3 blk(256);

    // 1-3: kv + kr projections, rope on kr
    gemm_tf32<<<dim3(8, 32), blk, GEMM_SMEM_BYTES>>>(x, Dd, Wkv, bkv, kvb, 2*LATd, Mrows, 2*LATd, Dd);
    gemm_tf32<<<dim3(1, 32), blk, GEMM_SMEM_BYTES>>>(x, Dd, Wkr, bkr, krb, RDd,    Mrows, RDd,    Dd);
    rope_kr_kernel<<<Mrows, 32>>>(krb);

    // 4: the big q projection (ncu target slot)
    gemm_tf32<<<dim3(16, 32), blk, GEMM_SMEM_BYTES>>>(x, Dd, Wq,  bq,  qb,  Hh*HDd, Mrows, Hh*HDd, Dd);

    // 5-7: up-projections, rope on q
    gemm_tf32<<<dim3(8,  32), blk, GEMM_SMEM_BYTES>>>(kvb,        2*LATd, Wku, bku, kcb, Hh*CDd, Mrows, Hh*CDd, LATd);
    gemm_tf32<<<dim3(16, 32), blk, GEMM_SMEM_BYTES>>>(kvb + LATd, 2*LATd, Wvu, bvu, vb,  Hh*HDd, Mrows, Hh*HDd, LATd);
    rope_q_kernel<<<dim3(Mrows, Hh), 32>>>(qb);

    // 8: attention (128-row q blocks)
    attn_mma_kernel<<<dim3(Tt/128, Hh, Bb), blk, A2_SMEM_BYTES>>>(qb, kcb, krb, vb, ob);

    // 9: output projection
    gemm_tf32<<<dim3(16, 32), blk, GEMM_SMEM_BYTES>>>(ob, Hh*HDd, Wo, bo, out, Dd, Mrows, Dd, Dd);
}

// round 10
// speedup vs baseline: 1.3865x; 1.0304x over previous
#include <cuda_runtime.h>
#include <cuda_bf16.h>
#include <math.h>
#include <stdint.h>

// Problem constants
#define Bb   2
#define Tt   2048
#define Dd   2048
#define Hh   16
#define HDd  128
#define LATd 512
#define RDd  64
#define CDd  64
#define Mrows (Bb*Tt)   // 4096

// ---------------------------------------------------------------------------
// Scratch (static device globals; no allocation allowed)
// ---------------------------------------------------------------------------
__device__ float g_q [Mrows * (Hh*HDd)];
__device__ float g_kv[Mrows * (2*LATd)];
__device__ float g_kr[Mrows * RDd];
__device__ float g_kc[Mrows * (Hh*CDd)];
__device__ float g_v [Mrows * (Hh*HDd)];
__device__ float g_ao[Mrows * (Hh*HDd)];

// ---------------------------------------------------------------------------
// Common tf32 helpers (fragment layouts HW-validated rounds 3-9)
// ---------------------------------------------------------------------------
__device__ __forceinline__ uint32_t f2tf32(float f) {
    uint32_t r;
    asm("cvt.rna.tf32.f32 %0, %1;" : "=r"(r) : "f"(f));
    return r;
}

__device__ __forceinline__ void mma_tf32(
    float& c0, float& c1, float& c2, float& c3,
    uint32_t a0, uint32_t a1, uint32_t a2, uint32_t a3,
    uint32_t b0, uint32_t b1)
{
    asm volatile(
        "mma.sync.aligned.m16n8k8.row.col.f32.tf32.tf32.f32 "
        "{%0,%1,%2,%3}, {%4,%5,%6,%7}, {%8,%9}, {%0,%1,%2,%3};\n"
        : "+f"(c0), "+f"(c1), "+f"(c2), "+f"(c3)
        : "r"(a0), "r"(a1), "r"(a2), "r"(a3), "r"(b0), "r"(b1));
}

__device__ __forceinline__ void cp_async16(uint32_t dst_smem, const void* src, int src_bytes) {
    asm volatile("cp.async.cg.shared.global [%0], [%1], 16, %2;\n"
                 :: "r"(dst_smem), "l"(src), "r"(src_bytes));
}
#define CP_COMMIT() asm volatile("cp.async.commit_group;\n" ::: "memory")
#define CP_WAIT1()  asm volatile("cp.async.wait_group 1;\n" ::: "memory")

// ---------------------------------------------------------------------------
// TF32 GEMM core: C(:, 0..Nloc) = A(M,K) @ W(Nloc,K)^T + bias
// 128x128x32 tiles, 256 threads, warp tile 64x32.
// 3-stage cp.async pipeline, ONE __syncthreads per k-tile:
//   wait(own groups<=1) -> barrier -> prefetch(t+2) -> compute(t)
// The barrier both publishes stage t's data and guarantees all warps finished
// compute(t-1) before anyone overwrites stage (t+2)%3 == (t-1)%3.
// ---------------------------------------------------------------------------
#define BM 128
#define BN 128
#define BK 32
#define GST 36
#define G_ASZ (BM*GST)
#define GSTG 3
#define GEMM_SMEM_BYTES (GSTG * 2 * G_ASZ * 4)   // 110592 B (2 CTAs = 221 KB/SM)

__device__ __forceinline__ void gemm_core(
    const float* __restrict__ A, int lda,
    const float* __restrict__ W,      // section base (rows 0..Nloc)
    const float* __restrict__ bias,   // section base
    float* __restrict__ C, int ldc,   // section base
    int Nloc, int K, int bm, int bnl,
    float* smemf)
{
    const uint32_t smem_u32 = (uint32_t)__cvta_generic_to_shared(smemf);

    const int tid  = threadIdx.x;
    const int warp = tid >> 5;
    const int lane = tid & 31;
    const int g    = lane >> 2;
    const int tg   = lane & 3;
    const int wm   = warp & 1;
    const int wn   = warp >> 1;
    const int wr0  = wm * 64;
    const int wn0  = wn * 32;

    const int lrow0 = tid >> 3;
    const int lk4   = (tid & 7) * 4;

    float acc[4][4][4];
    #pragma unroll
    for (int mi = 0; mi < 4; mi++)
        #pragma unroll
        for (int ni = 0; ni < 4; ni++)
            #pragma unroll
            for (int r = 0; r < 4; r++) acc[mi][ni][r] = 0.f;

    const int ntiles = K / BK;

    auto prefetch = [&](int k0, int s) {
        #pragma unroll
        for (int it = 0; it < 4; it++) {
            int row = lrow0 + it * 32;
            uint32_t adst = smem_u32 + (uint32_t)((s*G_ASZ + row*GST + lk4) * 4);
            cp_async16(adst, A + (size_t)(bm + row) * lda + k0 + lk4, 16);
            int nrow = bnl + row;
            uint32_t bdst = smem_u32 + (uint32_t)(((GSTG + s)*G_ASZ + row*GST + lk4) * 4);
            cp_async16(bdst, W + (size_t)(nrow < Nloc ? nrow : 0) * K + k0 + lk4,
                       nrow < Nloc ? 16 : 0);
        }
    };

    prefetch(0, 0);      CP_COMMIT();
    prefetch(BK, 1);     CP_COMMIT();

    int st = 0, ps = 2;
    for (int t = 0; t < ntiles; t++) {
        CP_WAIT1();
        __syncthreads();
        if (t + 2 < ntiles) prefetch((t + 2) * BK, ps);
        CP_COMMIT();

        const float* Asb = smemf + st * G_ASZ;
        const float* Bsb = smemf + (GSTG + st) * G_ASZ;

        #pragma unroll
        for (int kk = 0; kk < BK; kk += 8) {
            uint32_t af[4][4], bf[4][2];
            #pragma unroll
            for (int mi = 0; mi < 4; mi++) {
                int r0 = wr0 + mi * 16 + g;
                af[mi][0] = f2tf32(Asb[r0*GST       + kk + tg]);
                af[mi][1] = f2tf32(Asb[(r0+8)*GST   + kk + tg]);
                af[mi][2] = f2tf32(Asb[r0*GST       + kk + tg + 4]);
                af[mi][3] = f2tf32(Asb[(r0+8)*GST   + kk + tg + 4]);
            }
            #pragma unroll
            for (int ni = 0; ni < 4; ni++) {
                int n0 = wn0 + ni * 8 + g;
                bf[ni][0] = f2tf32(Bsb[n0*GST + kk + tg]);
                bf[ni][1] = f2tf32(Bsb[n0*GST + kk + tg + 4]);
            }
            #pragma unroll
            for (int mi = 0; mi < 4; mi++)
                #pragma unroll
                for (int ni = 0; ni < 4; ni++)
                    mma_tf32(acc[mi][ni][0], acc[mi][ni][1],
                             acc[mi][ni][2], acc[mi][ni][3],
                             af[mi][0], af[mi][1], af[mi][2], af[mi][3],
                             bf[ni][0], bf[ni][1]);
        }
        st = (st == 2) ? 0 : st + 1;
        ps = (ps == 2) ? 0 : ps + 1;
    }

    #pragma unroll
    for (int mi = 0; mi < 4; mi++) {
        int row0 = bm + wr0 + mi * 16 + g;
        #pragma unroll
        for (int ni = 0; ni < 4; ni++) {
            int col = bnl + wn0 + ni * 8 + 2 * tg;
            if (col < Nloc) {
                float b0 = bias[col];
                float b1 = bias[col + 1];
                float* p0 = C + (size_t)row0 * ldc + col;
                float* p1 = C + (size_t)(row0 + 8) * ldc + col;
                p0[0] = acc[mi][ni][0] + b0;
                p0[1] = acc[mi][ni][1] + b1;
                p1[0] = acc[mi][ni][2] + b0;
                p1[1] = acc[mi][ni][3] + b1;
            }
        }
    }
}

// ---- wrapper: plain GEMM (output projection) ----
__global__ void __launch_bounds__(256, 2) gemm_plain(
    const float* __restrict__ A, int lda,
    const float* __restrict__ W,
    const float* __restrict__ bias,
    float* __restrict__ C, int ldc,
    int N, int K)
{
    extern __shared__ float smemf[];
    gemm_core(A, lda, W, bias, C, ldc, N, K,
              blockIdx.y * BM, blockIdx.x * BN, smemf);
}

// ---- wrapper: fused q | kv | kr projection (N sections 2048 | 1024 | 64) ----
__global__ void __launch_bounds__(256, 2) gemm_qkvkr(
    const float* __restrict__ x,
    const float* __restrict__ Wq,  const float* __restrict__ bq,
    const float* __restrict__ Wkv, const float* __restrict__ bkv,
    const float* __restrict__ Wkr, const float* __restrict__ bkr,
    float* __restrict__ qb, float* __restrict__ kvb, float* __restrict__ krb)
{
    extern __shared__ float smemf[];
    int bn = blockIdx.x * BN;
    const float *W, *bias; float* C; int ldc, Nloc, bnl;
    if (bn < 2048)      { W = Wq;  bias = bq;  C = qb;  ldc = 2048; Nloc = 2048; bnl = bn; }
    else if (bn < 3072) { W = Wkv; bias = bkv; C = kvb; ldc = 1024; Nloc = 1024; bnl = bn - 2048; }
    else                { W = Wkr; bias = bkr; C = krb; ldc = 64;   Nloc = 64;   bnl = bn - 3072; }
    gemm_core(x, Dd, W, bias, C, ldc, Nloc, Dd, blockIdx.y * BM, bnl, smemf);
}

// ---- wrapper: fused ku | vu up-projection (N sections 1024 | 2048, K=512) ----
__global__ void __launch_bounds__(256, 2) gemm_kuvu(
    const float* __restrict__ kvb,
    const float* __restrict__ Wku, const float* __restrict__ bku,
    const float* __restrict__ Wvu, const float* __restrict__ bvu,
    float* __restrict__ kcb, float* __restrict__ vb)
{
    extern __shared__ float smemf[];
    int bn = blockIdx.x * BN;
    const float* A; const float *W, *bias; float* C; int ldc, Nloc, bnl;
    if (bn < 1024) { A = kvb;        W = Wku; bias = bku; C = kcb; ldc = 1024; Nloc = 1024; bnl = bn; }
    else           { A = kvb + LATd; W = Wvu; bias = bvu; C = vb;  ldc = 2048; Nloc = 2048; bnl = bn - 1024; }
    gemm_core(A, 2*LATd, W, bias, C, ldc, Nloc, LATd, blockIdx.y * BM, bnl, smemf);
}

// ---------------------------------------------------------------------------
// RoPE (rotate-half). RD=64, half=32. One kernel for kr + all q heads.
// ---------------------------------------------------------------------------
__device__ __forceinline__ void rope_pair(float* p, int i, int t)
{
    float inv_freq = powf(10000.f, -(float)i / 32.f);
    float ang = (float)t * inv_freq;
    float s, c;
    sincosf(ang, &s, &c);
    float x1 = p[i];
    float x2 = p[i + 32];
    p[i]      = x1 * c - x2 * s;
    p[i + 32] = x2 * c + x1 * s;
}

__global__ void rope_all(float* __restrict__ qb, float* __restrict__ kr)
{
    int row = blockIdx.x;
    int h   = blockIdx.y;
    int t   = row & (Tt - 1);
    if (h == Hh)
        rope_pair(kr + (size_t)row * RDd, threadIdx.x, t);
    else
        rope_pair(qb + (size_t)row * (Hh*HDd) + h*HDd + CDd, threadIdx.x, t);
}

// ---------------------------------------------------------------------------
// Tensor-core flash attention, 128-row q blocks, cp.async double-buffered K/V.
// (unchanged from rounds 7/9)
// ---------------------------------------------------------------------------
#define A2_SK 132
#define A2_SV 136
#define A2_SP 68
#define A2_KSZ (64*A2_SK)
#define A2_VSZ (64*A2_SV)
#define A2_SMEM_BYTES ((2*A2_KSZ + 2*A2_VSZ + 128*A2_SP) * 4)

__global__ void __launch_bounds__(256, 1) attn_mma_kernel(
    const float* __restrict__ q,
    const float* __restrict__ kc,
    const float* __restrict__ kr,
    const float* __restrict__ v,
    float* __restrict__ o)
{
    extern __shared__ float smf[];
    float*    Ksf = smf;
    float*    Vsf = smf + 2*A2_KSZ;
    uint32_t* Ps  = (uint32_t*)(smf + 2*A2_KSZ + 2*A2_VSZ);
    const uint32_t smem_u32 = (uint32_t)__cvta_generic_to_shared(smf);

    const int qt   = (Tt/128 - 1) - blockIdx.x;
    const int h    = blockIdx.y;
    const int b    = blockIdx.z;
    const int tid  = threadIdx.x;
    const int warp = tid >> 5;
    const int lane = tid & 31;
    const int g    = lane >> 2;
    const int tg   = lane & 3;
    const int m0   = warp * 16;
    const int qbase = qt * 128;
    const size_t rowbase = (size_t)b * Tt;
    const float scale = 0.08838834764831845f;

    uint32_t aq[16][4];
    {
        const float* qA = q + (rowbase + qbase + m0 + g) * (Hh*HDd) + h*HDd;
        const float* qB = qA + 8 * (Hh*HDd);
        #pragma unroll
        for (int ks = 0; ks < 16; ks++) {
            int k0 = ks * 8;
            aq[ks][0] = f2tf32(qA[k0 + tg]);
            aq[ks][1] = f2tf32(qB[k0 + tg]);
            aq[ks][2] = f2tf32(qA[k0 + tg + 4]);
            aq[ks][3] = f2tf32(qB[k0 + tg + 4]);
        }
    }

    float oacc[16][4];
    #pragma unroll
    for (int na = 0; na < 16; na++)
        #pragma unroll
        for (int r = 0; r < 4; r++) oacc[na][r] = 0.f;

    float mA = -INFINITY, mB = -INFINITY;
    float lA = 0.f, lB = 0.f;

    const int rAg = qbase + m0 + g;
    const int rBg = rAg + 8;
    const int ntiles = 2*qt + 2;

    auto prefetch = [&](int kb, int s) {
        const int kbase = kb * 64;
        #pragma unroll
        for (int it = 0; it < 8; it++) {
            int i  = tid + it * 256;
            int rr = i >> 5;
            int c4 = i & 31;
            size_t trow = rowbase + kbase + rr;
            const float* ksrc = (c4 < 16)
                ? (kc + trow * (Hh*CDd) + h*CDd + c4*4)
                : (kr + trow * RDd + (c4-16)*4);
            uint32_t kdst = smem_u32 + (uint32_t)((s*A2_KSZ + rr*A2_SK + c4*4) * 4);
            cp_async16(kdst, ksrc, 16);
            const float* vsrc = v + trow * (Hh*HDd) + h*HDd + c4*4;
            uint32_t vdst = smem_u32 + (uint32_t)((2*A2_KSZ + s*A2_VSZ + rr*A2_SV + c4*4) * 4);
            cp_async16(vdst, vsrc, 16);
        }
    };

    prefetch(0, 0);
    CP_COMMIT();

    for (int kb = 0; kb < ntiles; kb++) {
        if (kb + 1 < ntiles) prefetch(kb + 1, (kb + 1) & 1);
        CP_COMMIT();
        CP_WAIT1();
        __syncthreads();

        const int kbase = kb * 64;
        const float* Kst = Ksf + (kb & 1) * A2_KSZ;
        const float* Vst = Vsf + (kb & 1) * A2_VSZ;

        const bool active = (kbase <= qbase + m0 + 15);
        if (active) {
            float sacc[8][4];
            #pragma unroll
            for (int na = 0; na < 8; na++)
                #pragma unroll
                for (int r = 0; r < 4; r++) sacc[na][r] = 0.f;

            #pragma unroll
            for (int ks = 0; ks < 16; ks++) {
                #pragma unroll
                for (int na = 0; na < 8; na++) {
                    uint32_t b0 = f2tf32(Kst[(na*8 + g)*A2_SK + ks*8 + tg]);
                    uint32_t b1 = f2tf32(Kst[(na*8 + g)*A2_SK + ks*8 + tg + 4]);
                    mma_tf32(sacc[na][0], sacc[na][1], sacc[na][2], sacc[na][3],
                             aq[ks][0], aq[ks][1], aq[ks][2], aq[ks][3], b0, b1);
                }
            }

            const bool needmask = (kbase + 63 > rAg);
            float mxA = -INFINITY, mxB = -INFINITY;
            #pragma unroll
            for (int na = 0; na < 8; na++) {
                float s0 = sacc[na][0] * scale;
                float s1 = sacc[na][1] * scale;
                float s2 = sacc[na][2] * scale;
                float s3 = sacc[na][3] * scale;
                if (needmask) {
                    int cg = kbase + na*8 + 2*tg;
                    if (cg     > rAg) s0 = -INFINITY;
                    if (cg + 1 > rAg) s1 = -INFINITY;
                    if (cg     > rBg) s2 = -INFINITY;
                    if (cg + 1 > rBg) s3 = -INFINITY;
                }
                sacc[na][0] = s0; sacc[na][1] = s1;
                sacc[na][2] = s2; sacc[na][3] = s3;
                mxA = fmaxf(mxA, fmaxf(s0, s1));
                mxB = fmaxf(mxB, fmaxf(s2, s3));
            }
            mxA = fmaxf(mxA, __shfl_xor_sync(0xffffffff, mxA, 1));
            mxA = fmaxf(mxA, __shfl_xor_sync(0xffffffff, mxA, 2));
            mxB = fmaxf(mxB, __shfl_xor_sync(0xffffffff, mxB, 1));
            mxB = fmaxf(mxB, __shfl_xor_sync(0xffffffff, mxB, 2));

            float mnA = fmaxf(mA, mxA);
            float mnB = fmaxf(mB, mxB);
            float cfA = __expf(mA - mnA);
            float cfB = __expf(mB - mnB);
            mA = mnA; mB = mnB;

            float sumA = 0.f, sumB = 0.f;
            uint32_t* prowA = Ps + (m0 + g) * A2_SP;
            uint32_t* prowB = prowA + 8 * A2_SP;
            #pragma unroll
            for (int na = 0; na < 8; na++) {
                int c = na*8 + 2*tg;
                float p0 = __expf(sacc[na][0] - mA);
                float p1 = __expf(sacc[na][1] - mA);
                float p2 = __expf(sacc[na][2] - mB);
                float p3 = __expf(sacc[na][3] - mB);
                sumA += p0 + p1;
                sumB += p2 + p3;
                prowA[c]     = f2tf32(p0);
                prowA[c + 1] = f2tf32(p1);
                prowB[c]     = f2tf32(p2);
                prowB[c + 1] = f2tf32(p3);
            }
            lA = lA * cfA + sumA;
            lB = lB * cfB + sumB;

            #pragma unroll
            for (int na = 0; na < 16; na++) {
                oacc[na][0] *= cfA; oacc[na][1] *= cfA;
                oacc[na][2] *= cfB; oacc[na][3] *= cfB;
            }

            __syncwarp();

            #pragma unroll
            for (int ks = 0; ks < 8; ks++) {
                uint32_t pa0 = Ps[(m0 + g)     * A2_SP + ks*8 + tg];
                uint32_t pa1 = Ps[(m0 + g + 8) * A2_SP + ks*8 + tg];
                uint32_t pa2 = Ps[(m0 + g)     * A2_SP + ks*8 + tg + 4];
                uint32_t pa3 = Ps[(m0 + g + 8) * A2_SP + ks*8 + tg + 4];
                #pragma unroll
                for (int na = 0; na < 16; na++) {
                    uint32_t b0 = f2tf32(Vst[(ks*8 + tg)     * A2_SV + na*8 + g]);
                    uint32_t b1 = f2tf32(Vst[(ks*8 + tg + 4) * A2_SV + na*8 + g]);
                    mma_tf32(oacc[na][0], oacc[na][1], oacc[na][2], oacc[na][3],
                             pa0, pa1, pa2, pa3, b0, b1);
                }
            }
        }
        __syncthreads();
    }

    lA += __shfl_xor_sync(0xffffffff, lA, 1);
    lA += __shfl_xor_sync(0xffffffff, lA, 2);
    lB += __shfl_xor_sync(0xffffffff, lB, 1);
    lB += __shfl_xor_sync(0xffffffff, lB, 2);
    float invA = 1.f / lA;
    float invB = 1.f / lB;

    float* oA = o + (rowbase + qbase + m0 + g) * (Hh*HDd) + h*HDd;
    float* oB = oA + 8 * (Hh*HDd);
    #pragma unroll
    for (int na = 0; na < 16; na++) {
        int c = na*8 + 2*tg;
        *(float2*)(oA + c) = make_float2(oacc[na][0]*invA, oacc[na][1]*invA);
        *(float2*)(oB + c) = make_float2(oacc[na][2]*invB, oacc[na][3]*invB);
    }
}

// ---------------------------------------------------------------------------
// Launch: 5 launches total; attention is launch 4 (ncu slot).
// ---------------------------------------------------------------------------
extern "C" void kernel_launch(void* const* d_in, const int* in_sizes, int n_in,
                              void* d_out, int out_size)
{
    const float* x   = (const float*)d_in[0];
    const float* Wq  = (const float*)d_in[1];
    const float* bq  = (const float*)d_in[2];
    const float* Wkv = (const float*)d_in[3];
    const float* bkv = (const float*)d_in[4];
    const float* Wkr = (const float*)d_in[5];
    const float* bkr = (const float*)d_in[6];
    const float* Wku = (const float*)d_in[7];
    const float* bku = (const float*)d_in[8];
    const float* Wvu = (const float*)d_in[9];
    const float* bvu = (const float*)d_in[10];
    const float* Wo  = (const float*)d_in[11];
    const float* bo  = (const float*)d_in[12];
    float* out = (float*)d_out;

    float *qb, *kvb, *krb, *kcb, *vb, *ob;
    cudaGetSymbolAddress((void**)&qb,  g_q);
    cudaGetSymbolAddress((void**)&kvb, g_kv);
    cudaGetSymbolAddress((void**)&krb, g_kr);
    cudaGetSymbolAddress((void**)&kcb, g_kc);
    cudaGetSymbolAddress((void**)&vb,  g_v);
    cudaGetSymbolAddress((void**)&ob,  g_ao);

    cudaFuncSetAttribute(gemm_plain,
                         cudaFuncAttributeMaxDynamicSharedMemorySize, GEMM_SMEM_BYTES);
    cudaFuncSetAttribute(gemm_qkvkr,
                         cudaFuncAttributeMaxDynamicSharedMemorySize, GEMM_SMEM_BYTES);
    cudaFuncSetAttribute(gemm_kuvu,
                         cudaFuncAttributeMaxDynamicSharedMemorySize, GEMM_SMEM_BYTES);
    cudaFuncSetAttribute(attn_mma_kernel,
                         cudaFuncAttributeMaxDynamicSharedMemorySize, A2_SMEM_BYTES);

    const dim3 blk(256);

    // 1: fused q|kv|kr projection (N = 2048+1024+64 = 3136 -> 25 col blocks)
    gemm_qkvkr<<<dim3(25, 32), blk, GEMM_SMEM_BYTES>>>(
        x, Wq, bq, Wkv, bkv, Wkr, bkr, qb, kvb, krb);

    // 2: fused ku|vu up-projection (N = 1024+2048 = 3072 -> 24 col blocks)
    gemm_kuvu<<<dim3(24, 32), blk, GEMM_SMEM_BYTES>>>(
        kvb, Wku, bku, Wvu, bvu, kcb, vb);

    // 3: rope on kr + q (one launch)
    rope_all<<<dim3(Mrows, Hh + 1), 32>>>(qb, krb);

    // 4: attention (ncu target slot)
    attn_mma_kernel<<<dim3(Tt/128, Hh, Bb), blk, A2_SMEM_BYTES>>>(qb, kcb, krb, vb, ob);

    // 5: output projection
    gemm_plain<<<dim3(16, 32), blk, GEMM_SMEM_BYTES>>>(
        ob, Hh*HDd, Wo, bo, out, Dd, Mrows, Dd);
}